// round 5
// baseline (speedup 1.0000x reference)
#include <cuda_runtime.h>

// N=8192 rows, C=5000 classes, RATIO=3
#define NC       5000
#define NT       256
#define NW       8
#define CAP      1024
#define HSTRIDE  260   // bytes per bin row (65 words): word bank = (bin + tid/4) & 31

__device__ double   g_loss = 0.0;
__device__ double   g_tsum = 0.0;
__device__ unsigned g_done = 0;

// order-preserving float->uint key (larger float <-> larger key)
__device__ __forceinline__ unsigned fkey(float f) {
    unsigned b = __float_as_uint(f);
    return (b & 0x80000000u) ? ~b : (b | 0x80000000u);
}
__device__ __forceinline__ float kinv(unsigned k) {
    return __uint_as_float((k & 0x80000000u) ? (k & 0x7FFFFFFFu) : ~k);
}
// fast softplus (MUFU-based)
__device__ __forceinline__ float sp(float x) {
    float l = __logf(1.f + __expf(-fabsf(x)));
    return x > 0.f ? x + l : l;
}
// sum of 4 packed bytes into acc
__device__ __forceinline__ unsigned dp4a_acc(unsigned v, unsigned acc) {
    unsigned r;
    asm("dp4a.u32.u32 %0, %1, %2, %3;" : "=r"(r) : "r"(v), "r"(0x01010101u), "r"(acc));
    return r;
}

__global__ void __launch_bounds__(NT)
hardneg(const float* __restrict__ pred, const float* __restrict__ target,
        float* __restrict__ out)
{
    __shared__ unsigned      s_key[NC];            // 20000 B (0 marker = positive)
    __shared__ unsigned char s_h8[64 * HSTRIDE];   // 16640 B private byte histograms
    __shared__ unsigned      s_cand[CAP];          //  4096 B
    __shared__ unsigned      s_c1[64];
    __shared__ unsigned      s_c2[64];
    __shared__ int           s_posr[NW];
    __shared__ float         s_accr[NW];
    __shared__ unsigned      s_bc, s_kk1, s_bf, s_kk2, s_tkey, s_krem;
    __shared__ int           s_cnt;

    const int tid  = threadIdx.x;
    const int lane = tid & 31;
    const int wid  = tid >> 5;
    const int row  = blockIdx.x;

    const float4* p4 = (const float4*)(pred   + (size_t)row * NC);
    const float4* t4 = (const float4*)(target + (size_t)row * NC);

    // ---- zero private histogram (16640 B = 4160 words) ----
    unsigned* hw = (unsigned*)s_h8;
    for (int i = tid; i < 64 * HSTRIDE / 4; i += NT) hw[i] = 0;
    if (tid == 0) s_cnt = 0;
    __syncthreads();

    // ---- load pass: keys, positive BCE, stage-1 private histogram (neg only) ----
    int   poscnt = 0;
    float accP   = 0.f;
    uint4* k4s = (uint4*)s_key;

    #define PROC(px, tx, kout)                                              \
        do {                                                                \
            float _x = (px);                                                \
            if ((tx) != 0.f) {                                              \
                poscnt++; accP += sp(_x) - _x; (kout) = 0u;                 \
            } else {                                                        \
                unsigned _k = fkey(_x); (kout) = _k;                        \
                s_h8[(_k >> 26) * HSTRIDE + tid]++;                         \
            }                                                               \
        } while (0)

    for (int i = tid; i < NC / 4; i += NT) {
        float4 p = p4[i];
        float4 t = t4[i];
        uint4  k;
        PROC(p.x, t.x, k.x);
        PROC(p.y, t.y, k.y);
        PROC(p.z, t.z, k.z);
        PROC(p.w, t.w, k.w);
        k4s[i] = k;
    }
    #undef PROC

    // positive count reduce (no barrier needed yet for this)
    int pc = poscnt;
    #pragma unroll
    for (int off = 16; off; off >>= 1) pc += __shfl_down_sync(0xFFFFFFFFu, pc, off);
    if (lane == 0) s_posr[wid] = pc;
    __syncthreads();

    // ---- stage-1 reduce: 64 bin totals via dp4a ----
    if (tid < 64) {
        const unsigned* rw = (const unsigned*)(s_h8 + tid * HSTRIDE);
        unsigned acc = 0;
        #pragma unroll
        for (int j = 0; j < 64; j++) acc = dp4a_acc(rw[j], acc);
        s_c1[tid] = acc;
    }
    __syncthreads();

    int post = 0;
    #pragma unroll
    for (int w = 0; w < NW; w++) post += s_posr[w];
    int k0 = 3 * post;
    if (k0 > NC - post) k0 = NC - post;
    const unsigned kk = (unsigned)k0;

    // ---- stage-1 select coarse bin + re-zero histogram for stage 2 ----
    if (k0 > 0 && tid < 64) {
        unsigned above = 0;
        for (int b = tid + 1; b < 64; b++) above += s_c1[b];
        unsigned c = s_c1[tid];
        if (above < kk && kk <= above + c) { s_bc = (unsigned)tid; s_kk1 = kk - above; }
    }
    for (int i = tid; i < 64 * HSTRIDE / 4; i += NT) hw[i] = 0;
    __syncthreads();

    // ---- stage-2: private histogram of fine bin within coarse bin ----
    if (k0 > 0) {
        const unsigned bc = s_bc;
        const uint4* kr = (const uint4*)s_key;
        #define H2(kc)                                                       \
            if ((kc) != 0u && ((kc) >> 26) == bc)                            \
                s_h8[(((kc) >> 20) & 63u) * HSTRIDE + tid]++;
        for (int i = tid; i < NC / 4; i += NT) {
            uint4 kv = kr[i];
            H2(kv.x) H2(kv.y) H2(kv.z) H2(kv.w)
        }
        #undef H2
    }
    __syncthreads();

    if (k0 > 0 && tid < 64) {
        const unsigned* rw = (const unsigned*)(s_h8 + tid * HSTRIDE);
        unsigned acc = 0;
        #pragma unroll
        for (int j = 0; j < 64; j++) acc = dp4a_acc(rw[j], acc);
        s_c2[tid] = acc;
    }
    __syncthreads();

    if (k0 > 0 && tid < 64) {
        const unsigned kk1 = s_kk1;
        unsigned above = 0;
        for (int b = tid + 1; b < 64; b++) above += s_c2[b];
        unsigned c = s_c2[tid];
        if (above < kk1 && kk1 <= above + c) { s_bf = (unsigned)tid; s_kk2 = kk1 - above; }
    }
    __syncthreads();

    // ---- pass B (fused): above-bin softplus + gather threshold-bin candidates ----
    float acc = accP;
    if (k0 > 0) {
        const unsigned tb = (s_bc << 6) | s_bf;   // 12-bit bin id at key>>20 granularity
        const uint4* kr = (const uint4*)s_key;
        #define G(kc)                                                        \
            do {                                                             \
                unsigned _h = (kc) >> 20;                                    \
                if (_h > tb) acc += sp(kinv(kc));                            \
                else if (_h == tb && (kc) != 0u) {                           \
                    int s = atomicAdd(&s_cnt, 1);                            \
                    if (s < CAP) s_cand[s] = (kc);                           \
                }                                                            \
            } while (0)
        for (int i = tid; i < NC / 4; i += NT) {
            uint4 kv = kr[i];
            G(kv.x); G(kv.y); G(kv.z); G(kv.w);
        }
        #undef G
    }
    __syncthreads();

    // ---- exact kk2-th largest among candidates (rank counting) ----
    if (k0 > 0) {
        int M = s_cnt; if (M > CAP) M = CAP;
        const unsigned kk2 = s_kk2;
        for (int c = tid; c < M; c += NT) {
            unsigned key = s_cand[c];
            unsigned gt = 0, eq = 0;
            for (int j = 0; j < M; j++) {
                unsigned o = s_cand[j];
                gt += (o > key);
                eq += (o == key);
            }
            if (gt < kk2 && kk2 <= gt + eq) { s_tkey = key; s_krem = kk2 - gt; }
        }
    }
    __syncthreads();

    // ---- in-bin selected candidates ----
    if (k0 > 0) {
        const unsigned tk = s_tkey;
        int M = s_cnt; if (M > CAP) M = CAP;
        for (int c = tid; c < M; c += NT) {
            unsigned key = s_cand[c];
            if (key > tk) acc += sp(kinv(key));
        }
    }

    // ---- block reduce + global accumulate + last-block finalize ----
    #pragma unroll
    for (int off = 16; off; off >>= 1) acc += __shfl_down_sync(0xFFFFFFFFu, acc, off);
    if (lane == 0) s_accr[wid] = acc;
    __syncthreads();

    if (tid == 0) {
        float totL = 0.f;
        #pragma unroll
        for (int w = 0; w < NW; w++) totL += s_accr[w];
        if (k0 > 0) totL += (float)s_krem * sp(kinv(s_tkey));  // exact tie correction
        atomicAdd(&g_loss, (double)totL);
        atomicAdd(&g_tsum, (double)post);
        __threadfence();
        unsigned done = atomicAdd(&g_done, 1u);
        if (done == gridDim.x - 1) {
            double L = atomicAdd(&g_loss, 0.0);   // forced memory reads
            double T = atomicAdd(&g_tsum, 0.0);
            out[0] = (float)(L / T);
            // reset for next graph replay (deterministic)
            atomicExch((unsigned long long*)&g_loss, 0ull);
            atomicExch((unsigned long long*)&g_tsum, 0ull);
            __threadfence();
            atomicExch(&g_done, 0u);
        }
    }
}

extern "C" void kernel_launch(void* const* d_in, const int* in_sizes, int n_in,
                              void* d_out, int out_size) {
    const float* pred   = (const float*)d_in[0];
    const float* target = (const float*)d_in[1];
    float* out = (float*)d_out;
    int rows = in_sizes[0] / NC;

    hardneg<<<rows, NT>>>(pred, target, out);
}

// round 6
// speedup vs baseline: 1.3954x; 1.3954x over previous
#include <cuda_runtime.h>

// N=8192 rows, C=5000 classes, RATIO=3
#define NC    5000
#define NT    256
#define NW    8
#define NV    5      // ceil(1250 float4 / 256 threads)
#define NV4   1250   // float4 count per row
#define HW    2048   // histogram words: 4096 bins, two 16-bit counts per word
#define CAP   1024   // threshold-bin candidate capacity (expected ~50-120)

__device__ double   g_loss = 0.0;
__device__ double   g_tsum = 0.0;
__device__ unsigned g_done = 0;

// order-preserving float->uint key (larger float <-> larger key)
__device__ __forceinline__ unsigned fkey(float f) {
    unsigned b = __float_as_uint(f);
    return (b & 0x80000000u) ? ~b : (b | 0x80000000u);
}
__device__ __forceinline__ float kinv(unsigned k) {
    return __uint_as_float((k & 0x80000000u) ? (k & 0x7FFFFFFFu) : ~k);
}
// fast softplus (MUFU-based)
__device__ __forceinline__ float sp(float x) {
    float l = __logf(1.f + __expf(-fabsf(x)));
    return x > 0.f ? x + l : l;
}

__global__ void __launch_bounds__(NT)
hardneg(const float* __restrict__ pred, const float* __restrict__ target,
        float* __restrict__ out)
{
    __shared__ unsigned s_hist[HW];    // 8192 B : packed 16-bit counts (4096 bins)
    __shared__ unsigned s_cand[CAP];   // 4096 B
    __shared__ unsigned s_wsum[NW];
    __shared__ int      s_posr[NW];
    __shared__ float    s_accr[NW];
    __shared__ unsigned s_binv, s_kkv, s_tkey, s_krem;
    __shared__ int      s_cnt;

    const int tid  = threadIdx.x;
    const int lane = tid & 31;
    const int wid  = tid >> 5;
    const int row  = blockIdx.x;

    const float4* p4 = (const float4*)(pred   + (size_t)row * NC);
    const float4* t4 = (const float4*)(target + (size_t)row * NC);

    // zero histogram (vectorized)
    uint4* h4 = (uint4*)s_hist;
    #pragma unroll
    for (int j = 0; j < HW / 4 / NT; j++) h4[tid + j * NT] = make_uint4(0, 0, 0, 0);
    if (tid == 0) s_cnt = 0;
    __syncthreads();

    // ---- pass A: load, classify, key (REGISTERS), histogram, positive BCE ----
    int   poscnt = 0;
    float accP   = 0.f;
    uint4 kreg[NV];

    #define PROC(px, tx, kout)                                             \
        do {                                                               \
            float _x = (px);                                               \
            if ((tx) != 0.f) {                                             \
                poscnt++; accP += sp(_x) - _x; (kout) = 0u;                \
            } else {                                                       \
                unsigned _k = fkey(_x); (kout) = _k;                       \
                atomicAdd(&s_hist[_k >> 21],                               \
                          ((_k >> 20) & 1u) ? 65536u : 1u);                \
            }                                                              \
        } while (0)

    #pragma unroll
    for (int j = 0; j < NV; j++) {
        int i = j * NT + tid;
        uint4 k = make_uint4(0, 0, 0, 0);
        if (j < NV - 1 || i < NV4) {
            float4 p = p4[i];
            float4 t = t4[i];
            PROC(p.x, t.x, k.x);
            PROC(p.y, t.y, k.y);
            PROC(p.z, t.z, k.z);
            PROC(p.w, t.w, k.w);
        }
        kreg[j] = k;
    }
    #undef PROC
    __syncthreads();

    // ---- locate threshold bin: suffix counts via shuffle scan ----
    // thread t owns bins [t*16, t*16+16) = words [t*8, t*8+8)
    unsigned w8[8];
    unsigned S = 0;
    #pragma unroll
    for (int j = 0; j < 8; j++) {
        unsigned v = s_hist[tid * 8 + j];
        w8[j] = v;
        S += (v & 0xFFFFu) + (v >> 16);
    }
    unsigned v = S;  // inclusive suffix within warp
    #pragma unroll
    for (int off = 1; off < 32; off <<= 1) {
        unsigned o = __shfl_down_sync(0xFFFFFFFFu, v, off);
        if (lane + off < 32) v += o;
    }
    if (lane == 0) s_wsum[wid] = v;

    int pc = poscnt;
    #pragma unroll
    for (int off = 16; off; off >>= 1) pc += __shfl_down_sync(0xFFFFFFFFu, pc, off);
    if (lane == 0) s_posr[wid] = pc;
    __syncthreads();

    int post = 0;
    #pragma unroll
    for (int w = 0; w < NW; w++) post += s_posr[w];
    int k0 = 3 * post;
    if (k0 > NC - post) k0 = NC - post;

    unsigned above = v - S;  // bins above mine within my warp
    #pragma unroll
    for (int w = wid + 1; w < NW; w++) above += s_wsum[w];

    if (k0 > 0) {
        unsigned kk = (unsigned)k0;
        if (above < kk && kk <= above + S) {
            unsigned a = above;
            #pragma unroll
            for (int j = 15; j >= 0; j--) {   // walk my 16 bins from the top
                unsigned wv = w8[j >> 1];
                unsigned c  = (j & 1) ? (wv >> 16) : (wv & 0xFFFFu);
                if (kk <= a + c) { s_binv = (unsigned)(tid * 16 + j); s_kkv = kk - a; break; }
                a += c;
            }
        }
    }
    __syncthreads();

    // ---- pass B (from registers): above-bin softplus + gather threshold-bin ----
    float acc = accP;
    if (k0 > 0) {
        const unsigned bsel = s_binv;
        #define G(kc)                                                          \
            do {                                                               \
                unsigned _b = (kc) >> 20;                                      \
                if (_b > bsel) acc += sp(kinv(kc));                            \
                else if (_b == bsel && (kc) != 0u) {                           \
                    int s = atomicAdd(&s_cnt, 1);                              \
                    if (s < CAP) s_cand[s] = (kc);                             \
                }                                                              \
            } while (0)
        #pragma unroll
        for (int j = 0; j < NV; j++) {
            uint4 kv = kreg[j];
            G(kv.x); G(kv.y); G(kv.z); G(kv.w);
        }
        #undef G
    }
    __syncthreads();

    // ---- exact k-th largest among candidates (rank counting) ----
    if (k0 > 0) {
        int M = s_cnt; if (M > CAP) M = CAP;
        const unsigned kk = s_kkv;
        for (int c = tid; c < M; c += NT) {
            unsigned key = s_cand[c];
            unsigned gt = 0, eq = 0;
            for (int j = 0; j < M; j++) {
                unsigned o = s_cand[j];
                gt += (o > key);
                eq += (o == key);
            }
            if (gt < kk && kk <= gt + eq) { s_tkey = key; s_krem = kk - gt; }
        }
    }
    __syncthreads();

    // ---- in-bin selected candidates ----
    if (k0 > 0) {
        const unsigned tk = s_tkey;
        int M = s_cnt; if (M > CAP) M = CAP;
        for (int c = tid; c < M; c += NT) {
            unsigned key = s_cand[c];
            if (key > tk) acc += sp(kinv(key));
        }
    }

    // ---- block reduce + global accumulate + last-block finalize ----
    #pragma unroll
    for (int off = 16; off; off >>= 1) acc += __shfl_down_sync(0xFFFFFFFFu, acc, off);
    if (lane == 0) s_accr[wid] = acc;
    __syncthreads();

    if (tid == 0) {
        float totL = 0.f;
        #pragma unroll
        for (int w = 0; w < NW; w++) totL += s_accr[w];
        if (k0 > 0) totL += (float)s_krem * sp(kinv(s_tkey));  // exact tie correction
        atomicAdd(&g_loss, (double)totL);
        atomicAdd(&g_tsum, (double)post);
        __threadfence();
        unsigned done = atomicAdd(&g_done, 1u);
        if (done == gridDim.x - 1) {
            double L = atomicAdd(&g_loss, 0.0);   // forced memory reads
            double T = atomicAdd(&g_tsum, 0.0);
            out[0] = (float)(L / T);
            // reset for next graph replay (deterministic)
            atomicExch((unsigned long long*)&g_loss, 0ull);
            atomicExch((unsigned long long*)&g_tsum, 0ull);
            __threadfence();
            atomicExch(&g_done, 0u);
        }
    }
}

extern "C" void kernel_launch(void* const* d_in, const int* in_sizes, int n_in,
                              void* d_out, int out_size) {
    const float* pred   = (const float*)d_in[0];
    const float* target = (const float*)d_in[1];
    float* out = (float*)d_out;
    int rows = in_sizes[0] / NC;

    hardneg<<<rows, NT>>>(pred, target, out);
}